// round 8
// baseline (speedup 1.0000x reference)
#include <cuda_runtime.h>
#include <cuda_fp16.h>
#include <cstdint>

// Live computation: out[B*S, E] = x @ Wout + bout  (attention in reference is dead code)
// M=8192, N=512, K=512, fp32 in/out.
// Single-term fp16 GEMM: out = fp16(x) @ fp16(W) + bias (fp32 accum).
// Measured (R6/R7): rel_err 2.93e-4 << 1e-3 gate.
#define MM 8192
#define NN 512
#define KK 512
#define TM 128
#define TN 128

// fp16 operands (device globals: allocation-free contract)
__device__ __align__(16) __half g_A[(size_t)MM * KK];   // 8 MB, m-major
__device__ __align__(16) __half g_B[(size_t)NN * KK];   // 0.5 MB, n-major (W transposed)

// ---------------------------------------------------------------------------
// Helpers (baseline sm_100: cp.async / ldmatrix / mma.sync)
// ---------------------------------------------------------------------------
__device__ __forceinline__ uint32_t smem_u32(const void* p) {
    uint32_t r;
    asm("{ .reg .u64 t; cvta.to.shared.u64 t, %1; cvt.u32.u64 %0, t; }" : "=r"(r) : "l"(p));
    return r;
}
__device__ __forceinline__ uint32_t sw128(uint32_t off) { return off ^ ((off >> 3) & 0x70); }

__device__ __forceinline__ void cp16(uint32_t dst, const void* src) {
    asm volatile("cp.async.cg.shared.global [%0], [%1], 16;" :: "r"(dst), "l"(src) : "memory");
}
__device__ __forceinline__ void cp_commit() {
    asm volatile("cp.async.commit_group;" ::: "memory");
}
__device__ __forceinline__ void cp_wait1() {
    asm volatile("cp.async.wait_group 1;" ::: "memory");
}
__device__ __forceinline__ void ldsm_x4(uint32_t* r, uint32_t addr) {
    asm volatile("ldmatrix.sync.aligned.m8n8.x4.shared.b16 {%0,%1,%2,%3}, [%4];"
                 : "=r"(r[0]), "=r"(r[1]), "=r"(r[2]), "=r"(r[3]) : "r"(addr));
}
__device__ __forceinline__ void mma16816(float* c, const uint32_t* a, uint32_t b0, uint32_t b1) {
    asm volatile(
        "mma.sync.aligned.m16n8k16.row.col.f32.f16.f16.f32 "
        "{%0,%1,%2,%3}, {%4,%5,%6,%7}, {%8,%9}, {%0,%1,%2,%3};"
        : "+f"(c[0]), "+f"(c[1]), "+f"(c[2]), "+f"(c[3])
        : "r"(a[0]), "r"(a[1]), "r"(a[2]), "r"(a[3]), "r"(b0), "r"(b1));
}

// ---------------------------------------------------------------------------
// Fused prep: blocks [0,2048) convert x -> g_A (8 floats/thread, streaming);
//             blocks [2048,2304) convert+transpose Wout -> g_B.
// ---------------------------------------------------------------------------
#define XBLOCKS 2048
__global__ void __launch_bounds__(256) prep(const float* __restrict__ x,
                                            const float* __restrict__ W) {
    int b = blockIdx.x;
    if (b < XBLOCKS) {
        int idx = b * 256 + threadIdx.x;             // over float8: MM*KK/8
        const float4* src = reinterpret_cast<const float4*>(x) + (size_t)idx * 2;
        float4 v0 = src[0], v1 = src[1];
        __half2 h0 = __floats2half2_rn(v0.x, v0.y);
        __half2 h1 = __floats2half2_rn(v0.z, v0.w);
        __half2 h2 = __floats2half2_rn(v1.x, v1.y);
        __half2 h3 = __floats2half2_rn(v1.z, v1.w);
        uint4 o;
        o.x = *reinterpret_cast<uint32_t*>(&h0);
        o.y = *reinterpret_cast<uint32_t*>(&h1);
        o.z = *reinterpret_cast<uint32_t*>(&h2);
        o.w = *reinterpret_cast<uint32_t*>(&h3);
        *reinterpret_cast<uint4*>(&g_A[(size_t)idx * 8]) = o;
    } else {
        int idx = (b - XBLOCKS) * 256 + threadIdx.x; // over NN*KK/4
        int n = idx >> 7;
        int k = (idx & 127) << 2;
        __half h[4];
#pragma unroll
        for (int i = 0; i < 4; ++i)
            h[i] = __float2half_rn(W[(size_t)(k + i) * NN + n]);
        uint2 u;
        u.x = (uint32_t)__half_as_ushort(h[0]) | ((uint32_t)__half_as_ushort(h[1]) << 16);
        u.y = (uint32_t)__half_as_ushort(h[2]) | ((uint32_t)__half_as_ushort(h[3]) << 16);
        *reinterpret_cast<uint2*>(&g_B[(size_t)n * KK + k]) = u;
    }
}

// ---------------------------------------------------------------------------
// GEMM: 128x128 CTA tile, 512 threads = 16 warps in a 4x4 grid (32x32 warp
// tiles -> 32 accum regs/thread), 8 k64 chunks, 3-stage cp.async pipeline,
// one __syncthreads per chunk.
// SMEM: [0,512) bias; then 3 stages x (A 16K + B 16K) = 98816 B.
// ---------------------------------------------------------------------------
#define SM_BIAS 0
#define SM_T 512
#define STAGE_BYTES 32768
#define SMEM_BYTES (512 + 3 * STAGE_BYTES)

__global__ void __launch_bounds__(512, 2) gemm_kernel(const float* __restrict__ bout,
                                                      float* __restrict__ out) {
    extern __shared__ char smem[];
    const uint32_t sb = smem_u32(smem);
    const int tid = threadIdx.x;
    const int lane = tid & 31;
    const int wid = tid >> 5;          // 0..15
    const int warp_m = wid & 3;        // 0..3 -> rows warp_m*32
    const int warp_n = wid >> 2;       // 0..3 -> cols warp_n*32
    const int m_blk = blockIdx.x >> 2, n_blk = blockIdx.x & 3;
    const int m_base = m_blk * TM, n_base = n_blk * TN;

    if (tid < TN) reinterpret_cast<float*>(smem + SM_BIAS)[tid] = bout[n_base + tid];

    auto pref = [&](int kb) {
        const uint32_t st = sb + SM_T + (kb % 3) * STAGE_BYTES;
#pragma unroll
        for (int r = 0; r < 2; ++r) {
            int idx = tid + (r << 9);                // 0..1023
            int row = idx >> 3, c16 = idx & 7;
            uint32_t sw = sw128((uint32_t)(row * 128 + c16 * 16));
            cp16(st + sw,         g_A + (size_t)(m_base + row) * KK + kb * 64 + c16 * 8);
            cp16(st + 16384 + sw, g_B + (size_t)(n_base + row) * KK + kb * 64 + c16 * 8);
        }
    };

    pref(0); cp_commit();
    pref(1); cp_commit();

    float c[2][4][4];
#pragma unroll
    for (int mi = 0; mi < 2; ++mi)
#pragma unroll
        for (int ni = 0; ni < 4; ++ni)
#pragma unroll
            for (int q = 0; q < 4; ++q) c[mi][ni][q] = 0.f;

    for (int kb = 0; kb < 8; ++kb) {
        cp_wait1();                   // chunk kb resident (kb+1 may still be in flight)
        __syncthreads();              // all warps done reading the slot we're about to fill
        if (kb < 6) pref(kb + 2);     // fill freed slot, overlaps MMA below
        cp_commit();                  // empty groups near tail keep wait counts valid

        const uint32_t sa  = sb + SM_T + (kb % 3) * STAGE_BYTES;
        const uint32_t sbb = sa + 16384;
#pragma unroll
        for (int s = 0; s < 4; ++s) {                // k16 steps
            uint32_t a[2][4];
#pragma unroll
            for (int mi = 0; mi < 2; ++mi) {
                int row = warp_m * 32 + mi * 16 + (lane & 15);
                int kbyte = s * 32 + ((lane >> 4) << 4);
                ldsm_x4(a[mi], sa + sw128((uint32_t)(row * 128 + kbyte)));
            }
#pragma unroll
            for (int p = 0; p < 2; ++p) {            // n8 tile pairs (warp covers 32 cols)
                uint32_t b[4];
                int nrow = warp_n * 32 + p * 16 + ((lane >> 4) * 8 + (lane & 7));
                int kbyte = s * 32 + (((lane >> 3) & 1) << 4);
                ldsm_x4(b, sbb + sw128((uint32_t)(nrow * 128 + kbyte)));
                mma16816(c[0][2 * p],     a[0], b[0], b[1]);
                mma16816(c[0][2 * p + 1], a[0], b[2], b[3]);
                mma16816(c[1][2 * p],     a[1], b[0], b[1]);
                mma16816(c[1][2 * p + 1], a[1], b[2], b[3]);
            }
        }
    }

    // ---- epilogue: + bias, fp32 stores ----
    const float* bias = reinterpret_cast<const float*>(smem + SM_BIAS);
#pragma unroll
    for (int mi = 0; mi < 2; ++mi) {
        int gm0 = m_base + warp_m * 32 + mi * 16 + (lane >> 2);
#pragma unroll
        for (int ni = 0; ni < 4; ++ni) {
            int cn = warp_n * 32 + ni * 8 + ((lane & 3) << 1);
            int gn = n_base + cn;
            float b0 = bias[cn], b1 = bias[cn + 1];
            float2 v0 = make_float2(c[mi][ni][0] + b0, c[mi][ni][1] + b1);
            float2 v1 = make_float2(c[mi][ni][2] + b0, c[mi][ni][3] + b1);
            *reinterpret_cast<float2*>(out + (size_t)gm0 * NN + gn)       = v0;
            *reinterpret_cast<float2*>(out + (size_t)(gm0 + 8) * NN + gn) = v1;
        }
    }
}

// ---------------------------------------------------------------------------
// kernel_launch
// inputs: 0=x (fp32 4*2048*512), 1=attn_mask (dead), 2=Wqkv (dead),
//         3=bqkv (dead), 4=Wout (fp32 512*512), 5=bout (fp32 512)
// ---------------------------------------------------------------------------
extern "C" void kernel_launch(void* const* d_in, const int* in_sizes, int n_in,
                              void* d_out, int out_size) {
    const float* x    = (const float*)d_in[0];
    const float* Wout = (const float*)d_in[4];
    const float* bo   = (const float*)d_in[5];
    float* out = (float*)d_out;

    cudaFuncSetAttribute(gemm_kernel, cudaFuncAttributeMaxDynamicSharedMemorySize, SMEM_BYTES);

    prep<<<XBLOCKS + (NN * KK / 4) / 256, 256>>>(x, Wout);
    gemm_kernel<<<(MM / TM) * (NN / TN), 512, SMEM_BYTES>>>(bo, out);
}